// round 1
// baseline (speedup 1.0000x reference)
#include <cuda_runtime.h>
#include <math.h>

#define BS 8
#define CC 256
#define NN 1500
#define HH 8
#define DK 32

// ---------------- scratch (static device globals; no allocs) ----------------
__device__ float g_q[(size_t)BS * HH * NN * DK];           // [b][h][n][d]
__device__ float g_k[(size_t)BS * HH * NN * DK];
__device__ float g_v[(size_t)BS * HH * NN * DK];
__device__ float g_val[(size_t)BS * NN * CC];              // [b][n][c]
__device__ unsigned short g_nbr[(size_t)BS * NN * NN];     // per-row neighbor j lists
__device__ int g_cnt[BS * NN];

// ---------------- 1) mask + neighbor-list build (per batch, head-shared) ----
__global__ __launch_bounds__(256) void mask_kernel(const float* __restrict__ boxes,
                                                   const float* __restrict__ cm) {
    __shared__ float sx1[NN], sy1[NN], sx2[NN], sy2[NN], sa[NN], scm[NN];
    int b = blockIdx.y;
    const float4* bb = (const float4*)(boxes + (size_t)b * NN * 4);
    for (int idx = threadIdx.x; idx < NN; idx += blockDim.x) {
        float4 bx = bb[idx];                  // cx, cy, w, h
        float x1 = bx.x - 0.5f * bx.z;
        float x2 = bx.x + 0.5f * bx.z;
        float y1 = bx.y - 0.5f * bx.w;
        float y2 = bx.y + 0.5f * bx.w;
        sx1[idx] = x1; sx2[idx] = x2; sy1[idx] = y1; sy2[idx] = y2;
        sa[idx] = (x2 - x1) * (y2 - y1);
        scm[idx] = cm[(size_t)b * NN + idx];
    }
    __syncthreads();

    int warp = threadIdx.x >> 5, lane = threadIdx.x & 31;
    int i = blockIdx.x * 8 + warp;
    if (i >= NN) return;
    float x1i = sx1[i], x2i = sx2[i], y1i = sy1[i], y2i = sy2[i];
    float ai = sa[i], cmi = scm[i];
    unsigned short* out = g_nbr + ((size_t)b * NN + i) * NN;
    int cnt = 0;
    for (int jb = 0; jb < NN; jb += 32) {
        int j = jb + lane;
        bool nb = false;
        if (j < NN) {
            float ltx = fmaxf(x1i, sx1[j]);
            float lty = fmaxf(y1i, sy1[j]);
            float rbx = fminf(x2i, sx2[j]);
            float rby = fminf(y2i, sy2[j]);
            float iw = fmaxf(rbx - ltx, 0.0f);
            float ih = fmaxf(rby - lty, 0.0f);
            float inter = iw * ih;
            float uni = (ai + sa[j]) - inter;
            float iou = __fdiv_rn(inter, uni);     // IEEE RN regardless of fast-math
            float t = iou * cmi * scm[j];          // NaN -> compare false, as in ref
            nb = t > 0.5f;
        }
        unsigned bal = __ballot_sync(0xffffffffu, nb);
        int pos = cnt + __popc(bal & ((1u << lane) - 1u));
        if (nb) out[pos] = (unsigned short)j;
        cnt += __popc(bal);
    }
    if (lane == 0) g_cnt[b * NN + i] = cnt;
}

// ---------------- 2) QKV head projections -----------------------------------
__global__ __launch_bounds__(256) void qkv_kernel(const float* __restrict__ qin,
                                                  const float* __restrict__ kin,
                                                  const float* __restrict__ vin,
                                                  const float* __restrict__ wq,
                                                  const float* __restrict__ wk,
                                                  const float* __restrict__ wv) {
    __shared__ float4 sw[256];   // 32x32 weight matrix for this (mat, h)
    int mat = blockIdx.z;
    int bh = blockIdx.y;
    int b = bh >> 3, h = bh & 7;
    const float* W = (mat == 0 ? wq : (mat == 1 ? wk : wv)) + h * DK * DK;
    const float* X = (mat == 0 ? qin : (mat == 1 ? kin : vin));
    float* O = (mat == 0 ? g_q : (mat == 1 ? g_k : g_v));
    sw[threadIdx.x] = ((const float4*)W)[threadIdx.x];
    __syncthreads();

    int i = blockIdx.x * 256 + threadIdx.x;
    if (i >= NN) return;
    float x[DK];
    const float* xp = X + ((size_t)b * CC + h * DK) * NN + i;
#pragma unroll
    for (int j = 0; j < DK; j++) x[j] = xp[(size_t)j * NN];

    float out[DK];
#pragma unroll
    for (int d = 0; d < DK; d++) {
        float acc = 0.0f;
#pragma unroll
        for (int jq = 0; jq < 8; jq++) {
            float4 w4 = sw[d * 8 + jq];
            acc = fmaf(w4.x, x[jq * 4 + 0], acc);
            acc = fmaf(w4.y, x[jq * 4 + 1], acc);
            acc = fmaf(w4.z, x[jq * 4 + 2], acc);
            acc = fmaf(w4.w, x[jq * 4 + 3], acc);
        }
        out[d] = acc;
    }
    float4* op = (float4*)(O + ((size_t)bh * NN + i) * DK);
#pragma unroll
    for (int r = 0; r < 8; r++)
        op[r] = make_float4(out[r * 4], out[r * 4 + 1], out[r * 4 + 2], out[r * 4 + 3]);
}

// ---------------- 3) sparse masked attention (warp per query) ---------------
// Warp = 4 neighbor-groups (g=lane>>3) x 8 d-chunks (c=lane&7, 4 floats each).
__global__ __launch_bounds__(256) void attn_kernel() {
    int warp = threadIdx.x >> 5, lane = threadIdx.x & 31;
    int g = lane >> 3, c = lane & 7;
    int bh = blockIdx.y;
    int b = bh >> 3, h = bh & 7;
    int i = blockIdx.x * 8 + warp;
    if (i >= NN) return;

    int cnt = g_cnt[b * NN + i];
    float* valp = g_val + ((size_t)b * NN + i) * CC + h * DK;
    const float* vb = g_v + (size_t)bh * NN * DK;
    if (cnt == 0) {   // has_nb == 0 fallback: val = v
        float4 v4 = ((const float4*)(vb + (size_t)i * DK))[c];
        if (g == 0) ((float4*)valp)[c] = v4;
        return;
    }

    float4 q4 = ((const float4*)(g_q + ((size_t)bh * NN + i) * DK))[c];
    const unsigned short* nb = g_nbr + ((size_t)b * NN + i) * NN;
    const float* kb = g_k + (size_t)bh * NN * DK;

    // reference: max_val = max(attn * mask) -> masked zeros participate in max
    float m_run = (cnt < NN) ? 0.0f : -INFINITY;
    float l = 0.0f;
    float4 o = make_float4(0.f, 0.f, 0.f, 0.f);

    for (int t = 0; t < cnt; t += 4) {
        int jj = t + g;
        bool valid = jj < cnt;
        int j = nb[valid ? jj : (cnt - 1)];
        float4 k4 = ((const float4*)(kb + (size_t)j * DK))[c];
        float s = q4.x * k4.x + q4.y * k4.y + q4.z * k4.z + q4.w * k4.w;
        s += __shfl_xor_sync(0xffffffffu, s, 1);
        s += __shfl_xor_sync(0xffffffffu, s, 2);
        s += __shfl_xor_sync(0xffffffffu, s, 4);
        if (!valid) s = -INFINITY;
        float m4 = s;
        m4 = fmaxf(m4, __shfl_xor_sync(0xffffffffu, m4, 8));
        m4 = fmaxf(m4, __shfl_xor_sync(0xffffffffu, m4, 16));
        float m_new = fmaxf(m_run, m4);
        float scale = __expf(m_run - m_new);
        float p = __expf(s - m_new);          // invalid: exp(-inf)=0
        float4 v4 = ((const float4*)(vb + (size_t)j * DK))[c];
        l = l * scale + p;
        o.x = fmaf(p, v4.x, o.x * scale);
        o.y = fmaf(p, v4.y, o.y * scale);
        o.z = fmaf(p, v4.z, o.z * scale);
        o.w = fmaf(p, v4.w, o.w * scale);
        m_run = m_new;
    }
    // combine the 4 neighbor-groups (lanes differing in bits 3,4)
#define XRED(v) v += __shfl_xor_sync(0xffffffffu, v, 8); v += __shfl_xor_sync(0xffffffffu, v, 16);
    XRED(o.x) XRED(o.y) XRED(o.z) XRED(o.w) XRED(l)
#undef XRED
    float inv = 1.0f / (l + 1e-8f);
    o.x *= inv; o.y *= inv; o.z *= inv; o.w *= inv;
    if (g == 0) ((float4*)valp)[c] = o;
}

// ---------------- 4) output projection  out = Wp @ val + b ------------------
#define TI 64
#define TC 64
__global__ __launch_bounds__(256) void proj_kernel(const float* __restrict__ wp,
                                                   const float* __restrict__ bp,
                                                   float* __restrict__ out) {
    __shared__ float Ws[32][TC + 4];   // [ci][co]
    __shared__ float Vs[32][TI + 4];   // [ci][i]
    int b = blockIdx.z;
    int coT = blockIdx.y * TC;
    int iT = blockIdx.x * TI;
    int tx = threadIdx.x & 15;         // i-group
    int ty = threadIdx.x >> 4;         // co-group
    float acc[4][4] = {};

    for (int kc = 0; kc < CC; kc += 32) {
#pragma unroll
        for (int kk = 0; kk < 8; kk++) {
            int idx = threadIdx.x + kk * 256;     // 0..2047
            int row = idx >> 5;                   // co offset 0..63
            int col = idx & 31;                   // ci
            Ws[col][row] = wp[(size_t)(coT + row) * CC + kc + col];
        }
#pragma unroll
        for (int kk = 0; kk < 8; kk++) {
            int idx = threadIdx.x + kk * 256;
            int io = idx >> 5;
            int col = idx & 31;
            int gi = iT + io;
            Vs[col][io] = (gi < NN) ? g_val[((size_t)b * NN + gi) * CC + kc + col] : 0.0f;
        }
        __syncthreads();
#pragma unroll
        for (int ci = 0; ci < 32; ci++) {
            float4 w4 = *(const float4*)&Ws[ci][ty * 4];
            float4 v4 = *(const float4*)&Vs[ci][tx * 4];
            float wr[4] = {w4.x, w4.y, w4.z, w4.w};
            float vr[4] = {v4.x, v4.y, v4.z, v4.w};
#pragma unroll
            for (int a = 0; a < 4; a++)
#pragma unroll
                for (int e = 0; e < 4; e++)
                    acc[a][e] = fmaf(wr[a], vr[e], acc[a][e]);
        }
        __syncthreads();
    }

#pragma unroll
    for (int a = 0; a < 4; a++) {
        int co = coT + ty * 4 + a;
        float bias = bp[co];
        int gi = iT + tx * 4;
        if (gi < NN) {   // NN % 4 == 0, so whole float4 is valid
            float4 r = make_float4(acc[a][0] + bias, acc[a][1] + bias,
                                   acc[a][2] + bias, acc[a][3] + bias);
            *(float4*)&out[((size_t)b * CC + co) * NN + gi] = r;
        }
    }
}

// ---------------- launch ----------------------------------------------------
extern "C" void kernel_launch(void* const* d_in, const int* in_sizes, int n_in,
                              void* d_out, int out_size) {
    const float* queries = (const float*)d_in[0];
    const float* keys    = (const float*)d_in[1];
    const float* values  = (const float*)d_in[2];
    const float* boxes   = (const float*)d_in[3];
    const float* curmask = (const float*)d_in[4];
    const float* wq      = (const float*)d_in[5];
    const float* wk      = (const float*)d_in[6];
    const float* wv      = (const float*)d_in[7];
    const float* w_proj  = (const float*)d_in[8];
    const float* b_proj  = (const float*)d_in[9];
    float* out = (float*)d_out;

    mask_kernel<<<dim3(188, BS), 256>>>(boxes, curmask);
    qkv_kernel<<<dim3(6, BS * HH, 3), 256>>>(queries, keys, values, wq, wk, wv);
    attn_kernel<<<dim3(188, BS * HH), 256>>>();
    proj_kernel<<<dim3(24, CC / TC, BS), 256>>>(w_proj, b_proj, out);
}

// round 2
// speedup vs baseline: 1.0627x; 1.0627x over previous
#include <cuda_runtime.h>
#include <math.h>

#define BS 8
#define CC 256
#define NN 1500
#define HH 8
#define DK 32

// ---------------- scratch (static device globals; no allocs) ----------------
__device__ float g_q[(size_t)BS * HH * NN * DK];           // [b][h][n][d]
__device__ float g_k[(size_t)BS * HH * NN * DK];
__device__ float g_v[(size_t)BS * HH * NN * DK];
__device__ float g_val[(size_t)BS * NN * CC];              // [b][n][c]
__device__ unsigned short g_nbr[(size_t)BS * NN * NN];     // per-row neighbor j lists
__device__ int g_cnt[BS * NN];

// ---------------- 1) mask + neighbor-list build (per batch, head-shared) ----
__global__ __launch_bounds__(256) void mask_kernel(const float* __restrict__ boxes,
                                                   const float* __restrict__ cm) {
    __shared__ float sx1[NN], sy1[NN], sx2[NN], sy2[NN], sa[NN], scm[NN];
    int b = blockIdx.y;
    const float4* bb = (const float4*)(boxes + (size_t)b * NN * 4);
    for (int idx = threadIdx.x; idx < NN; idx += blockDim.x) {
        float4 bx = bb[idx];                  // cx, cy, w, h
        float x1 = bx.x - 0.5f * bx.z;
        float x2 = bx.x + 0.5f * bx.z;
        float y1 = bx.y - 0.5f * bx.w;
        float y2 = bx.y + 0.5f * bx.w;
        sx1[idx] = x1; sx2[idx] = x2; sy1[idx] = y1; sy2[idx] = y2;
        sa[idx] = (x2 - x1) * (y2 - y1);
        scm[idx] = cm[(size_t)b * NN + idx];
    }
    __syncthreads();

    int warp = threadIdx.x >> 5, lane = threadIdx.x & 31;
    int i = blockIdx.x * 8 + warp;
    if (i >= NN) return;
    float x1i = sx1[i], x2i = sx2[i], y1i = sy1[i], y2i = sy2[i];
    float ai = sa[i], cmi = scm[i];
    unsigned short* out = g_nbr + ((size_t)b * NN + i) * NN;
    int cnt = 0;
    for (int jb = 0; jb < NN; jb += 32) {
        int j = jb + lane;
        bool nb = false;
        if (j < NN) {
            float ltx = fmaxf(x1i, sx1[j]);
            float lty = fmaxf(y1i, sy1[j]);
            float rbx = fminf(x2i, sx2[j]);
            float rby = fminf(y2i, sy2[j]);
            float iw = fmaxf(rbx - ltx, 0.0f);
            float ih = fmaxf(rby - lty, 0.0f);
            float inter = iw * ih;
            float uni = (ai + sa[j]) - inter;
            float iou = __fdiv_rn(inter, uni);     // IEEE RN regardless of fast-math
            float t = iou * cmi * scm[j];          // NaN -> compare false, as in ref
            nb = t > 0.5f;
        }
        unsigned bal = __ballot_sync(0xffffffffu, nb);
        int pos = cnt + __popc(bal & ((1u << lane) - 1u));
        if (nb) out[pos] = (unsigned short)j;
        cnt += __popc(bal);
    }
    if (lane == 0) g_cnt[b * NN + i] = cnt;
}

// ---------------- 2) QKV head projections -----------------------------------
__global__ __launch_bounds__(256) void qkv_kernel(const float* __restrict__ qin,
                                                  const float* __restrict__ kin,
                                                  const float* __restrict__ vin,
                                                  const float* __restrict__ wq,
                                                  const float* __restrict__ wk,
                                                  const float* __restrict__ wv) {
    __shared__ float4 sw[256];   // 32x32 weight matrix for this (mat, h)
    int mat = blockIdx.z;
    int bh = blockIdx.y;
    int b = bh >> 3, h = bh & 7;
    const float* W = (mat == 0 ? wq : (mat == 1 ? wk : wv)) + h * DK * DK;
    const float* X = (mat == 0 ? qin : (mat == 1 ? kin : vin));
    float* O = (mat == 0 ? g_q : (mat == 1 ? g_k : g_v));
    sw[threadIdx.x] = ((const float4*)W)[threadIdx.x];
    __syncthreads();

    int i = blockIdx.x * 256 + threadIdx.x;
    if (i >= NN) return;
    float x[DK];
    const float* xp = X + ((size_t)b * CC + h * DK) * NN + i;
#pragma unroll
    for (int j = 0; j < DK; j++) x[j] = xp[(size_t)j * NN];

    float out[DK];
#pragma unroll
    for (int d = 0; d < DK; d++) {
        float acc = 0.0f;
#pragma unroll
        for (int jq = 0; jq < 8; jq++) {
            float4 w4 = sw[d * 8 + jq];
            acc = fmaf(w4.x, x[jq * 4 + 0], acc);
            acc = fmaf(w4.y, x[jq * 4 + 1], acc);
            acc = fmaf(w4.z, x[jq * 4 + 2], acc);
            acc = fmaf(w4.w, x[jq * 4 + 3], acc);
        }
        out[d] = acc;
    }
    float4* op = (float4*)(O + ((size_t)bh * NN + i) * DK);
#pragma unroll
    for (int r = 0; r < 8; r++)
        op[r] = make_float4(out[r * 4], out[r * 4 + 1], out[r * 4 + 2], out[r * 4 + 3]);
}

// ---------------- 3) sparse masked attention (warp per query) ---------------
// Warp = 4 neighbor-groups (g=lane>>3) x 8 d-chunks (c=lane&7, 4 floats each).
// Software-pipelined: next chunk's K/V gathers issue before the current
// reduction chain (index clamped to cnt-1 -> branch-free, always-valid loads).
__global__ __launch_bounds__(256) void attn_kernel() {
    int warp = threadIdx.x >> 5, lane = threadIdx.x & 31;
    int g = lane >> 3, c = lane & 7;
    int bh = blockIdx.y;
    int b = bh >> 3, h = bh & 7;
    int i = blockIdx.x * 8 + warp;
    if (i >= NN) return;

    int cnt = g_cnt[b * NN + i];
    float* valp = g_val + ((size_t)b * NN + i) * CC + h * DK;
    const float* vb = g_v + (size_t)bh * NN * DK;
    if (cnt == 0) {   // has_nb == 0 fallback: val = v
        float4 v4 = ((const float4*)(vb + (size_t)i * DK))[c];
        if (g == 0) ((float4*)valp)[c] = v4;
        return;
    }

    float4 q4 = ((const float4*)(g_q + ((size_t)bh * NN + i) * DK))[c];
    const unsigned short* nb = g_nbr + ((size_t)b * NN + i) * NN;
    const float* kb = g_k + (size_t)bh * NN * DK;
    int cm1 = cnt - 1;

    // reference: max_val = max(attn * mask) -> masked zeros participate in max
    float m_run = (cnt < NN) ? 0.0f : -INFINITY;
    float l = 0.0f;
    float4 o = make_float4(0.f, 0.f, 0.f, 0.f);

    // prologue: load chunk 0
    int j0 = nb[min(g, cm1)];
    float4 kcur = ((const float4*)(kb + (size_t)j0 * DK))[c];
    float4 vcur = ((const float4*)(vb + (size_t)j0 * DK))[c];

    for (int t = 0; t < cnt; t += 4) {
        // prefetch next chunk (clamped; extra loads hit cache, values unused)
        int jn = nb[min(t + 4 + g, cm1)];
        float4 knext = ((const float4*)(kb + (size_t)jn * DK))[c];
        float4 vnext = ((const float4*)(vb + (size_t)jn * DK))[c];

        bool valid = (t + g) < cnt;
        float s = q4.x * kcur.x + q4.y * kcur.y + q4.z * kcur.z + q4.w * kcur.w;
        s += __shfl_xor_sync(0xffffffffu, s, 1);
        s += __shfl_xor_sync(0xffffffffu, s, 2);
        s += __shfl_xor_sync(0xffffffffu, s, 4);
        if (!valid) s = -INFINITY;
        float m4 = s;
        m4 = fmaxf(m4, __shfl_xor_sync(0xffffffffu, m4, 8));
        m4 = fmaxf(m4, __shfl_xor_sync(0xffffffffu, m4, 16));
        float m_new = fmaxf(m_run, m4);
        float scale = __expf(m_run - m_new);
        float p = __expf(s - m_new);          // invalid: exp(-inf)=0
        l = l * scale + p;
        o.x = fmaf(p, vcur.x, o.x * scale);
        o.y = fmaf(p, vcur.y, o.y * scale);
        o.z = fmaf(p, vcur.z, o.z * scale);
        o.w = fmaf(p, vcur.w, o.w * scale);
        m_run = m_new;
        kcur = knext; vcur = vnext;
    }
    // combine the 4 neighbor-groups (lanes differing in bits 3,4)
#define XRED(v) v += __shfl_xor_sync(0xffffffffu, v, 8); v += __shfl_xor_sync(0xffffffffu, v, 16);
    XRED(o.x) XRED(o.y) XRED(o.z) XRED(o.w) XRED(l)
#undef XRED
    float inv = 1.0f / (l + 1e-8f);
    o.x *= inv; o.y *= inv; o.z *= inv; o.w *= inv;
    if (g == 0) ((float4*)valp)[c] = o;
}

// ---------------- 4) output projection  out = Wp @ val + b ------------------
// 128(co) x 64(i) tile, 128 threads, 8x8 per thread -> 2 flop/smem-byte (FFMA-bound).
#define PCO 128
#define PII 64
__global__ __launch_bounds__(128) void proj_kernel(const float* __restrict__ wp,
                                                   const float* __restrict__ bp,
                                                   float* __restrict__ out) {
    __shared__ float Ws[16][PCO + 4];   // [ci][co]
    __shared__ float Vs[16][PII + 4];   // [ci][i]
    int b = blockIdx.z;
    int coT = blockIdx.y * PCO;
    int iT = blockIdx.x * PII;
    int tx = threadIdx.x & 7;          // i group: tx*4 and tx*4+32
    int ty = threadIdx.x >> 3;         // co group (0..15): ty*4 and ty*4+64
    float acc[8][8] = {};

    int ci4 = (threadIdx.x & 3) * 4;
    int r0 = threadIdx.x >> 2;         // 0..31

    for (int kc = 0; kc < CC; kc += 16) {
#pragma unroll
        for (int p = 0; p < 4; p++) {
            int co_r = r0 + p * 32;
            float4 w = *(const float4*)&wp[(size_t)(coT + co_r) * CC + kc + ci4];
            Ws[ci4 + 0][co_r] = w.x; Ws[ci4 + 1][co_r] = w.y;
            Ws[ci4 + 2][co_r] = w.z; Ws[ci4 + 3][co_r] = w.w;
        }
#pragma unroll
        for (int p = 0; p < 2; p++) {
            int io = r0 + p * 32;
            int gi = iT + io;
            float4 v = make_float4(0.f, 0.f, 0.f, 0.f);
            if (gi < NN) v = *(const float4*)&g_val[((size_t)b * NN + gi) * CC + kc + ci4];
            Vs[ci4 + 0][io] = v.x; Vs[ci4 + 1][io] = v.y;
            Vs[ci4 + 2][io] = v.z; Vs[ci4 + 3][io] = v.w;
        }
        __syncthreads();
#pragma unroll
        for (int ci = 0; ci < 16; ci++) {
            float4 w0 = *(const float4*)&Ws[ci][ty * 4];
            float4 w1 = *(const float4*)&Ws[ci][64 + ty * 4];
            float4 v0 = *(const float4*)&Vs[ci][tx * 4];
            float4 v1 = *(const float4*)&Vs[ci][32 + tx * 4];
            float wr[8] = {w0.x, w0.y, w0.z, w0.w, w1.x, w1.y, w1.z, w1.w};
            float vr[8] = {v0.x, v0.y, v0.z, v0.w, v1.x, v1.y, v1.z, v1.w};
#pragma unroll
            for (int a = 0; a < 8; a++)
#pragma unroll
                for (int e = 0; e < 8; e++)
                    acc[a][e] = fmaf(wr[a], vr[e], acc[a][e]);
        }
        __syncthreads();
    }

#pragma unroll
    for (int a = 0; a < 8; a++) {
        int co = coT + (a < 4 ? (ty * 4 + a) : (64 + ty * 4 + (a - 4)));
        float bias = bp[co];
#pragma unroll
        for (int half = 0; half < 2; half++) {
            int gi = iT + (half == 0 ? tx * 4 : 32 + tx * 4);
            int e0 = half * 4;
            if (gi < NN) {   // NN % 4 == 0, whole float4 valid
                float4 r = make_float4(acc[a][e0 + 0] + bias, acc[a][e0 + 1] + bias,
                                       acc[a][e0 + 2] + bias, acc[a][e0 + 3] + bias);
                *(float4*)&out[((size_t)b * CC + co) * NN + gi] = r;
            }
        }
    }
}

// ---------------- launch ----------------------------------------------------
extern "C" void kernel_launch(void* const* d_in, const int* in_sizes, int n_in,
                              void* d_out, int out_size) {
    const float* queries = (const float*)d_in[0];
    const float* keys    = (const float*)d_in[1];
    const float* values  = (const float*)d_in[2];
    const float* boxes   = (const float*)d_in[3];
    const float* curmask = (const float*)d_in[4];
    const float* wq      = (const float*)d_in[5];
    const float* wk      = (const float*)d_in[6];
    const float* wv      = (const float*)d_in[7];
    const float* w_proj  = (const float*)d_in[8];
    const float* b_proj  = (const float*)d_in[9];
    float* out = (float*)d_out;

    mask_kernel<<<dim3(188, BS), 256>>>(boxes, curmask);
    qkv_kernel<<<dim3(6, BS * HH, 3), 256>>>(queries, keys, values, wq, wk, wv);
    attn_kernel<<<dim3(188, BS * HH), 256>>>();
    proj_kernel<<<dim3((NN + PII - 1) / PII, CC / PCO, BS), 128>>>(w_proj, b_proj, out);
}